// round 15
// baseline (speedup 1.0000x reference)
#include <cuda_runtime.h>

// ---------------------------------------------------------------------------
// ResidualVQ: B=8, D_IN=768, T=2048, RVQ=512, NQ=8, CS=1024, CD=256
//
// Bit-exactness strategy: every value feeding the argmin decision replicates
// the reference's fp32 arithmetic:
//   - all GEMMs: single-accumulator FMA chain, ascending k (matches Eigen /
//     cuBLAS sgemm accumulation), bias added as ONE separate rounding
//   - s = sum(enc*enc): sequential ascending c, square and add as SEPARATE
//     roundings (__fmul_rn / __fadd_rn; no FMA contraction)
//   - cbn = sum(cb*cb): same structure
//   - dist_k = fl( fl(s - 2*dot_k) + cbn_k ), argmin ascending k, first min
// ---------------------------------------------------------------------------

#define Bsz 8
#define Tsz 2048
#define BT  (Bsz*Tsz)          // 16384 columns
#define DIN 768
#define RVQ 512
#define NQ  8
#define CS  1024
#define CD  256

#define OUT_ELEMS ((size_t)Bsz*DIN*Tsz)   // 12,582,912

// scratch (__device__ globals; no runtime allocation)
__device__ float g_x  [(size_t)Bsz*RVQ*Tsz];   // 32 MB
__device__ float g_res[(size_t)Bsz*RVQ*Tsz];   // 32 MB
__device__ float g_ze [(size_t)Bsz*CD*Tsz];    // 16 MB
__device__ float g_sc [(size_t)Bsz*CS*Tsz];    // 64 MB (raw dot products)
__device__ float g_s  [BT];                    // ||enc||^2 per column
__device__ float g_cbn[NQ*CS];                 // ||cb||^2 per code
__device__ int   g_idx[NQ*BT];

#define XM_DIRECT 0
#define XM_GATHER 1
#define XM_DIFF   2
#define EP_STORE  0
#define EP_DUAL   1
#define EP_SUB    2
#define EP_RAW    3

// ---------------------------------------------------------------------------
// Generic fp32 GEMM:  C(B,M,T) (+)= A(M,K) @ X(K, columns)  [+ bias[m]]
// Accumulation: one fp32 accumulator per output element, FMA, ascending k.
// ---------------------------------------------------------------------------
template<int XMODE, int EMODE, int K>
__global__ void __launch_bounds__(256)
gemm_k(const float* __restrict__ A,
       const float* __restrict__ X,
       const float* __restrict__ X2,
       const int*   __restrict__ gidx,
       const float* __restrict__ bias,
       float* __restrict__ C,
       float* __restrict__ C2,
       int M)
{
    constexpr int BK = 16;
    __shared__ float As[2][BK][128];
    __shared__ float Xs[2][BK][128];

    const int tid  = threadIdx.x;
    const int col0 = blockIdx.x * 128;
    const int bm   = blockIdx.y;
    const int batch = col0 / Tsz;
    const int t0    = col0 - batch * Tsz;

    const float* Ab  = A + (size_t)bm * 128 * K;
    const float* Xb  = X + ((size_t)batch * K) * Tsz + t0;
    const float* Xb2 = X2;
    if (XMODE == XM_DIFF) Xb2 = X2 + ((size_t)batch * K) * Tsz + t0;

    // loader lane mapping
    const int a_row = tid >> 2;          // 0..63 (two passes -> 128 rows)
    const int a_vc  = (tid & 3) << 2;    // 0,4,8,12 (k offset)
    const int x_kr  = tid >> 5;          // 0..7  (two passes -> 16 k rows)
    const int x_c4  = (tid & 31) << 2;   // col offset, float4
    const int gc    = tid & 127;         // gather: column
    const int gkh   = (tid >> 7) << 3;   // gather: k half (0 or 8)
    int code = 0;
    if (XMODE == XM_GATHER) code = gidx[col0 + gc];

    // ---- prologue: tile 0 into buffer 0 ----
    {
        #pragma unroll
        for (int p = 0; p < 2; p++) {
            float4 v = *(const float4*)(Ab + (size_t)(a_row + p*64) * K + a_vc);
            As[0][a_vc+0][a_row+p*64] = v.x;
            As[0][a_vc+1][a_row+p*64] = v.y;
            As[0][a_vc+2][a_row+p*64] = v.z;
            As[0][a_vc+3][a_row+p*64] = v.w;
        }
        if (XMODE == XM_GATHER) {
            const float* r = X2 + (size_t)code * CD + gkh;
            float4 v0 = *(const float4*)(r);
            float4 v1 = *(const float4*)(r + 4);
            Xs[0][gkh+0][gc] = v0.x; Xs[0][gkh+1][gc] = v0.y;
            Xs[0][gkh+2][gc] = v0.z; Xs[0][gkh+3][gc] = v0.w;
            Xs[0][gkh+4][gc] = v1.x; Xs[0][gkh+5][gc] = v1.y;
            Xs[0][gkh+6][gc] = v1.z; Xs[0][gkh+7][gc] = v1.w;
        } else {
            #pragma unroll
            for (int p = 0; p < 2; p++) {
                int kr = x_kr + p*8;
                float4 v = *(const float4*)(Xb + (size_t)kr * Tsz + x_c4);
                if (XMODE == XM_DIFF) {
                    float4 w = *(const float4*)(Xb2 + (size_t)kr * Tsz + x_c4);
                    v.x -= w.x; v.y -= w.y; v.z -= w.z; v.w -= w.w;
                }
                *(float4*)&Xs[0][kr][x_c4] = v;
            }
        }
    }
    __syncthreads();

    float acc[8][8];
    #pragma unroll
    for (int i = 0; i < 8; i++)
        #pragma unroll
        for (int j = 0; j < 8; j++) acc[i][j] = 0.f;

    const int ty = tid >> 4;
    const int tx = tid & 15;
    constexpr int NK = K / BK;

    #pragma unroll 2
    for (int ki = 0; ki < NK; ki++) {
        const int buf = ki & 1;
        const bool next = (ki + 1 < NK);
        float4 ra0, ra1, rx0, rx1;
        if (next) {
            const int kk = (ki + 1) * BK;
            ra0 = *(const float4*)(Ab + (size_t)(a_row)      * K + kk + a_vc);
            ra1 = *(const float4*)(Ab + (size_t)(a_row + 64) * K + kk + a_vc);
            if (XMODE == XM_GATHER) {
                const float* r = X2 + (size_t)code * CD + kk + gkh;
                rx0 = *(const float4*)(r);
                rx1 = *(const float4*)(r + 4);
            } else {
                rx0 = *(const float4*)(Xb + (size_t)(kk + x_kr)     * Tsz + x_c4);
                rx1 = *(const float4*)(Xb + (size_t)(kk + x_kr + 8) * Tsz + x_c4);
                if (XMODE == XM_DIFF) {
                    float4 w0 = *(const float4*)(Xb2 + (size_t)(kk + x_kr)     * Tsz + x_c4);
                    float4 w1 = *(const float4*)(Xb2 + (size_t)(kk + x_kr + 8) * Tsz + x_c4);
                    rx0.x-=w0.x; rx0.y-=w0.y; rx0.z-=w0.z; rx0.w-=w0.w;
                    rx1.x-=w1.x; rx1.y-=w1.y; rx1.z-=w1.z; rx1.w-=w1.w;
                }
            }
        }
        // compute on current buffer (ascending k within tile)
        #pragma unroll
        for (int k = 0; k < BK; k++) {
            float4 a0 = *(const float4*)&As[buf][k][ty*8];
            float4 a1 = *(const float4*)&As[buf][k][ty*8+4];
            float4 x0 = *(const float4*)&Xs[buf][k][tx*8];
            float4 x1 = *(const float4*)&Xs[buf][k][tx*8+4];
            float av[8] = {a0.x,a0.y,a0.z,a0.w,a1.x,a1.y,a1.z,a1.w};
            float xv[8] = {x0.x,x0.y,x0.z,x0.w,x1.x,x1.y,x1.z,x1.w};
            #pragma unroll
            for (int i = 0; i < 8; i++)
                #pragma unroll
                for (int j = 0; j < 8; j++)
                    acc[i][j] = fmaf(av[i], xv[j], acc[i][j]);
        }
        if (next) {
            const int nb = buf ^ 1;
            As[nb][a_vc+0][a_row]    = ra0.x;
            As[nb][a_vc+1][a_row]    = ra0.y;
            As[nb][a_vc+2][a_row]    = ra0.z;
            As[nb][a_vc+3][a_row]    = ra0.w;
            As[nb][a_vc+0][a_row+64] = ra1.x;
            As[nb][a_vc+1][a_row+64] = ra1.y;
            As[nb][a_vc+2][a_row+64] = ra1.z;
            As[nb][a_vc+3][a_row+64] = ra1.w;
            if (XMODE == XM_GATHER) {
                Xs[nb][gkh+0][gc] = rx0.x; Xs[nb][gkh+1][gc] = rx0.y;
                Xs[nb][gkh+2][gc] = rx0.z; Xs[nb][gkh+3][gc] = rx0.w;
                Xs[nb][gkh+4][gc] = rx1.x; Xs[nb][gkh+5][gc] = rx1.y;
                Xs[nb][gkh+6][gc] = rx1.z; Xs[nb][gkh+7][gc] = rx1.w;
            } else {
                *(float4*)&Xs[nb][x_kr][x_c4]     = rx0;
                *(float4*)&Xs[nb][x_kr + 8][x_c4] = rx1;
            }
        }
        __syncthreads();
    }

    // ---- epilogue ----
    float* Cb = C + ((size_t)batch * M + (size_t)bm * 128) * Tsz + t0;
    #pragma unroll
    for (int i = 0; i < 8; i++) {
        const int row = ty * 8 + i;
        float4 v0, v1;
        if (EMODE == EP_RAW) {
            v0.x = acc[i][0]; v0.y = acc[i][1]; v0.z = acc[i][2]; v0.w = acc[i][3];
            v1.x = acc[i][4]; v1.y = acc[i][5]; v1.z = acc[i][6]; v1.w = acc[i][7];
        } else {
            const float bv = bias[bm * 128 + row];
            v0.x = __fadd_rn(acc[i][0], bv); v0.y = __fadd_rn(acc[i][1], bv);
            v0.z = __fadd_rn(acc[i][2], bv); v0.w = __fadd_rn(acc[i][3], bv);
            v1.x = __fadd_rn(acc[i][4], bv); v1.y = __fadd_rn(acc[i][5], bv);
            v1.z = __fadd_rn(acc[i][6], bv); v1.w = __fadd_rn(acc[i][7], bv);
        }
        float* dst = Cb + (size_t)row * Tsz + tx * 8;
        if (EMODE == EP_SUB) {
            float4 o0 = *(const float4*)dst;
            float4 o1 = *(const float4*)(dst + 4);
            o0.x = __fadd_rn(o0.x, -v0.x); o0.y = __fadd_rn(o0.y, -v0.y);
            o0.z = __fadd_rn(o0.z, -v0.z); o0.w = __fadd_rn(o0.w, -v0.w);
            o1.x = __fadd_rn(o1.x, -v1.x); o1.y = __fadd_rn(o1.y, -v1.y);
            o1.z = __fadd_rn(o1.z, -v1.z); o1.w = __fadd_rn(o1.w, -v1.w);
            *(float4*)dst       = o0;
            *(float4*)(dst + 4) = o1;
        } else {
            *(float4*)dst       = v0;
            *(float4*)(dst + 4) = v1;
            if (EMODE == EP_DUAL) {
                float* dst2 = C2 + ((size_t)batch * M + (size_t)bm * 128 + row) * Tsz + t0 + tx * 8;
                *(float4*)dst2       = v0;
                *(float4*)(dst2 + 4) = v1;
            }
        }
    }
}

// ---------------------------------------------------------------------------
// cbn[code] = sum(cb[code]^2): sequential ascending c, square & add as
// SEPARATE roundings (replicates elementwise-mul HLO followed by reduce).
// ---------------------------------------------------------------------------
__global__ void cnorm_k(const float* __restrict__ cb, float* __restrict__ cn)
{
    int code = blockIdx.x * 256 + threadIdx.x;   // 0..NQ*CS-1
    const float* r = cb + (size_t)code * CD;
    float acc = 0.f;
    #pragma unroll 8
    for (int c = 0; c < CD; c++) {
        float sq = __fmul_rn(r[c], r[c]);
        acc = __fadd_rn(acc, sq);
    }
    cn[code] = acc;
}

// ---------------------------------------------------------------------------
// s[col] = sum_c enc[col][c]^2 = sum_c ze[b][c][t]^2, sequential ascending c,
// separate mul/add roundings.
// ---------------------------------------------------------------------------
__global__ void colsq_k(const float* __restrict__ ze, float* __restrict__ s)
{
    int col = blockIdx.x * 256 + threadIdx.x;
    int b = col >> 11;                 // T = 2048
    int t = col & (Tsz - 1);
    const float* p = ze + ((size_t)b * CD) * Tsz + t;
    float acc = 0.f;
    #pragma unroll 8
    for (int c = 0; c < CD; c++) {
        float v  = p[(size_t)c * Tsz];
        float sq = __fmul_rn(v, v);
        acc = __fadd_rn(acc, sq);
    }
    s[col] = acc;
}

// ---------------------------------------------------------------------------
// argmin over dist_k = fl( fl(s - 2*dot_k) + cbn_k ), ascending k, first-min.
// 2 threads per column (k halves), ordered merge (lower half wins ties).
// ---------------------------------------------------------------------------
__global__ void argmin_k(const float* __restrict__ dot,
                         const float* __restrict__ scol,
                         const float* __restrict__ cbn,
                         int* __restrict__ gi, float* __restrict__ fo)
{
    __shared__ float cb2[CS];
    __shared__ float sval[256];
    __shared__ int   sidx[256];
    for (int i = threadIdx.x; i < CS; i += 256) cb2[i] = cbn[i];
    __syncthreads();

    int c    = threadIdx.x & 127;
    int half = threadIdx.x >> 7;
    int col  = blockIdx.x * 128 + c;
    int b    = col >> 11;
    int t    = col & (Tsz - 1);
    const float* d = dot + ((size_t)b * CS) * Tsz + t;
    const float  s = scol[col];

    int k0 = half * (CS / 2);
    float best = 3.4e38f;
    int   bi   = k0;
    #pragma unroll 4
    for (int k = k0; k < k0 + CS / 2; k++) {
        float dv = d[(size_t)k * Tsz];
        float dist = __fadd_rn(__fadd_rn(s, -__fmul_rn(2.0f, dv)), cb2[k]);
        if (dist < best) { best = dist; bi = k; }
    }
    sval[threadIdx.x] = best;
    sidx[threadIdx.x] = bi;
    __syncthreads();
    if (half == 0) {
        float v1 = sval[threadIdx.x + 128];
        if (v1 < best) { best = v1; bi = sidx[threadIdx.x + 128]; }
        gi[col] = bi;
        fo[col] = (float)bi;
    }
}

// ---------------------------------------------------------------------------
extern "C" void kernel_launch(void* const* d_in, const int* in_sizes, int n_in,
                              void* d_out, int out_size)
{
    (void)in_sizes; (void)n_in; (void)out_size;
    const float* z   = (const float*)d_in[0];  // (8,768,2048)
    const float* ipw = (const float*)d_in[1];  // (512,768)
    const float* ipb = (const float*)d_in[2];  // (512)
    const float* inw = (const float*)d_in[3];  // (8,256,512)
    const float* inb = (const float*)d_in[4];  // (8,256)
    const float* cb  = (const float*)d_in[5];  // (8,1024,256)
    const float* opw = (const float*)d_in[6];  // (8,512,256)
    const float* opb = (const float*)d_in[7];  // (8,512)
    const float* ow  = (const float*)d_in[8];  // (768,512)
    const float* ob  = (const float*)d_in[9];  // (768)
    float* out = (float*)d_out;                // [out(8,768,2048) | idx(8,8,2048)]

    float *px, *pres, *pze, *psc, *ps, *pcbn; int *pidx;
    cudaGetSymbolAddress((void**)&px,   g_x);
    cudaGetSymbolAddress((void**)&pres, g_res);
    cudaGetSymbolAddress((void**)&pze,  g_ze);
    cudaGetSymbolAddress((void**)&psc,  g_sc);
    cudaGetSymbolAddress((void**)&ps,   g_s);
    cudaGetSymbolAddress((void**)&pcbn, g_cbn);
    cudaGetSymbolAddress((void**)&pidx, g_idx);

    // code norms (all stages)
    cnorm_k<<<NQ * CS / 256, 256>>>(cb, pcbn);

    // input_proj -> res and x (dual store)
    gemm_k<XM_DIRECT, EP_DUAL, DIN><<<dim3(BT/128, RVQ/128), 256>>>(
        ipw, z, nullptr, nullptr, ipb, pres, px, RVQ);

    for (int q = 0; q < NQ; q++) {
        // ze = in_w[q] @ res + in_b[q]
        gemm_k<XM_DIRECT, EP_STORE, RVQ><<<dim3(BT/128, CD/128), 256>>>(
            inw + (size_t)q * CD * RVQ, pres, nullptr, nullptr,
            inb + q * CD, pze, nullptr, CD);
        // raw dot = cb[q] @ ze
        gemm_k<XM_DIRECT, EP_RAW, CD><<<dim3(BT/128, CS/128), 256>>>(
            cb + (size_t)q * CS * CD, pze, nullptr, nullptr,
            nullptr, psc, nullptr, CS);
        // s = ||enc||^2 per column (reference rounding structure)
        colsq_k<<<BT/256, 256>>>(pze, ps);
        // argmin over fl(fl(s - 2*dot) + cbn)
        argmin_k<<<BT/128, 256>>>(psc, ps, pcbn + q * CS,
                                  pidx + q * BT,
                                  out + OUT_ELEMS + (size_t)q * BT);
        // res -= out_w[q] @ cb[q][idx] + out_b[q]
        gemm_k<XM_GATHER, EP_SUB, CD><<<dim3(BT/128, RVQ/128), 256>>>(
            opw + (size_t)q * RVQ * CD, cb + (size_t)q * CS * CD,
            cb + (size_t)q * CS * CD, pidx + q * BT,
            opb + q * RVQ, pres, nullptr, RVQ);
    }

    // out = output_proj_w @ (x - res) + b
    gemm_k<XM_DIFF, EP_STORE, RVQ><<<dim3(BT/128, DIN/128), 256>>>(
        ow, px, pres, nullptr, ob, out, nullptr, DIN);
}